// round 7
// baseline (speedup 1.0000x reference)
#include <cuda_runtime.h>
#include <cstdint>

#define TPB 256
#define NWARP 8
#define TILE_E (NWARP * 64)     // 64 edges per warp
#define MAXN 50000

typedef unsigned long long u64;

// Per-node precomputed projections, COLUMN-PERMUTED for float4 fragment loads:
// slice0 [0:32)  = nf@We1[0:128]+be1 (src),  perm: q*8  + nt*2 + b
// slice1 [32:64) = nf@We1[128:256]   (dst),  same perm within slice
// slice2 [64:128)= nf@Wn1[0:128]+bn1 (pre2), perm: q*16 + nt*2 + b
__device__ __align__(16) float g_P[MAXN * 128];

// ------------------------------- helpers ----------------------------------
__device__ __forceinline__ uint32_t f2tf(float f) {   // RNA round to tf32
    uint32_t r; asm("cvt.rna.tf32.f32 %0, %1;" : "=r"(r) : "f"(f)); return r;
}
__device__ __forceinline__ void red4(float* p, float a, float b, float c, float d) {
    asm volatile("red.global.add.v4.f32 [%0], {%1,%2,%3,%4};"
                 :: "l"(p), "f"(a), "f"(b), "f"(c), "f"(d) : "memory");
}
__device__ __forceinline__ u64 pk2(float lo, float hi) {
    u64 r;
    asm("mov.b64 %0, {%1, %2};" : "=l"(r)
        : "r"(__float_as_uint(lo)), "r"(__float_as_uint(hi)));
    return r;
}
__device__ __forceinline__ float2 up2(u64 v) {
    unsigned lo, hi;
    asm("mov.b64 {%0, %1}, %2;" : "=r"(lo), "=r"(hi) : "l"(v));
    return make_float2(__uint_as_float(lo), __uint_as_float(hi));
}
__device__ __forceinline__ u64 fma2(u64 a, u64 b, u64 c) {
    u64 d;
    asm("fma.rn.f32x2 %0, %1, %2, %3;" : "=l"(d) : "l"(a), "l"(b), "l"(c));
    return d;
}
// D(16x8,f32) += A(16x8,tf32) @ B(8x8,tf32)
__device__ __forceinline__ void mma8(float* c, uint32_t a0, uint32_t a1,
                                     uint32_t a2, uint32_t a3,
                                     uint32_t b0, uint32_t b1) {
    asm volatile("mma.sync.aligned.m16n8k8.row.col.f32.tf32.tf32.f32 "
                 "{%0,%1,%2,%3}, {%4,%5,%6,%7}, {%8,%9}, {%0,%1,%2,%3};"
                 : "+f"(c[0]), "+f"(c[1]), "+f"(c[2]), "+f"(c[3])
                 : "r"(a0), "r"(a1), "r"(a2), "r"(a3), "r"(b0), "r"(b1));
}
// C-fragment (16x8) -> A-fragment of same tile (relu + tf32), register shuffles
__device__ __forceinline__ void frag_c2a(float c0, float c1, float c2, float c3,
                                         int lane, uint32_t a[4]) {
    const unsigned F = 0xFFFFFFFFu;
    uint32_t r0 = f2tf(fmaxf(c0, 0.f)), r1 = f2tf(fmaxf(c1, 0.f));
    uint32_t r2 = f2tf(fmaxf(c2, 0.f)), r3 = f2tf(fmaxf(c3, 0.f));
    int l1 = (lane & 28) | ((lane & 3) >> 1);
    int l2 = l1 + 2;
    bool odd = lane & 1;
    uint32_t s0 = __shfl_sync(F, r0, l1), s1 = __shfl_sync(F, r1, l1);
    uint32_t s2 = __shfl_sync(F, r2, l1), s3 = __shfl_sync(F, r3, l1);
    uint32_t t0 = __shfl_sync(F, r0, l2), t1 = __shfl_sync(F, r1, l2);
    uint32_t t2 = __shfl_sync(F, r2, l2), t3 = __shfl_sync(F, r3, l2);
    a[0] = odd ? s1 : s0;  a[1] = odd ? s3 : s2;
    a[2] = odd ? t1 : t0;  a[3] = odd ? t3 : t2;
}
// column permutation for g_P storage
__device__ __forceinline__ int permP(int j) {
    if (j < 64) {
        int s = j & 32, c = j & 31;
        return s + ((c >> 1) & 3) * 8 + (c >> 3) * 2 + (c & 1);
    }
    int c = j - 64;
    return 64 + ((c >> 1) & 3) * 16 + (c >> 3) * 2 + (c & 1);
}

// ---------------------------------------------------------------------------
// Precompute: 16 nodes/block, packed f32x2 over k-pairs (exact fp32).
// Stores permuted columns; also initializes out = node_features.
// ---------------------------------------------------------------------------
__global__ void __launch_bounds__(128) precompute_kernel(
    const float* __restrict__ nf,
    const float* __restrict__ We1,
    const float* __restrict__ be1,
    const float* __restrict__ Wn1,
    const float* __restrict__ bn1,
    float* __restrict__ out, int Nn)
{
    __shared__ float nfs[16][128];
    const int nb  = blockIdx.x * 16;
    const int tid = threadIdx.x;

    #pragma unroll
    for (int i = 0; i < 16; i++) {
        int n = nb + i;
        if (n < Nn) {
            float v = nf[n * 128 + tid];
            nfs[i][tid] = v;
            out[n * 128 + tid] = v;
        } else nfs[i][tid] = 0.f;
    }
    __syncthreads();

    const int j = tid;
    const float* wcol; int stride; float bias;
    if (j < 32)      { wcol = We1 + j;                 stride = 32; bias = be1[j]; }
    else if (j < 64) { wcol = We1 + 128 * 32 + (j-32); stride = 32; bias = 0.f; }
    else             { wcol = Wn1 + (j - 64);          stride = 64; bias = bn1[j-64]; }

    u64 acc2[16];
    #pragma unroll
    for (int i = 0; i < 16; i++) acc2[i] = pk2(bias, 0.f);

    #pragma unroll 2
    for (int k = 0; k < 128; k += 2) {
        u64 w2 = pk2(wcol[k * stride], wcol[(k + 1) * stride]);
        #pragma unroll
        for (int i = 0; i < 16; i++) {
            float2 v = *(const float2*)&nfs[i][k];
            acc2[i] = fma2(pk2(v.x, v.y), w2, acc2[i]);
        }
    }
    const int pj = permP(j);
    #pragma unroll
    for (int i = 0; i < 16; i++) {
        int n = nb + i;
        if (n < Nn) {
            float2 f = up2(acc2[i]);
            g_P[n * 128 + pj] = f.x + f.y;
        }
    }
}

// ---------------------------------------------------------------------------
// Edge kernel: persistent, 8 warps x 64 edges each (M=64 halves weight LDS
// per edge). mma.sync tf32; ef staged via smem; scatter via smem transpose.
// ---------------------------------------------------------------------------
#define OFF_W1  0            // [32][68]  -> 8704
#define OFF_W2  8704         // [128][36] -> 18432
#define OFF_W3  27136        // [64][132] -> 33792
#define OFF_W4  60928        // [128][68] -> 34816
#define OFF_BE2 95744
#define OFF_BN2 96256
#define OFF_SCR 96768
#define WS_BYTES 9216        // per-warp buffer [64][36] words (ef / h1 / nm)
#define SM_TOTAL (OFF_SCR + NWARP * WS_BYTES)   // 170496

__global__ void __launch_bounds__(TPB, 1) edge_mma_kernel(
    const float* __restrict__ ef,
    const int*   __restrict__ eidx,
    const float* __restrict__ We1,
    const float* __restrict__ We2,
    const float* __restrict__ be2,
    const float* __restrict__ Wn1,
    const float* __restrict__ Wn2,
    const float* __restrict__ bn2,
    float* __restrict__ out, int E, int ntiles)
{
    extern __shared__ char sm[];
    uint32_t* W1s = (uint32_t*)(sm + OFF_W1);
    uint32_t* W2s = (uint32_t*)(sm + OFF_W2);
    uint32_t* W3s = (uint32_t*)(sm + OFF_W3);
    uint32_t* W4s = (uint32_t*)(sm + OFF_W4);
    float* be2s = (float*)(sm + OFF_BE2);
    float* bn2s = (float*)(sm + OFF_BN2);

    const int tid = threadIdx.x;
    for (int i = tid; i < 32 * 64;  i += TPB) { int n = i >> 6, k = i & 63;  W1s[n*68  + k] = f2tf(We1[(256 + k) * 32 + n]); }
    for (int i = tid; i < 128 * 32; i += TPB) { int n = i >> 5, k = i & 31;  W2s[n*36  + k] = f2tf(We2[k * 128 + n]); }
    for (int i = tid; i < 64 * 128; i += TPB) { int n = i >> 7, k = i & 127; W3s[n*132 + k] = f2tf(Wn1[(128 + k) * 64 + n]); }
    for (int i = tid; i < 128 * 64; i += TPB) { int n = i >> 6, k = i & 63;  W4s[n*68  + k] = f2tf(Wn2[k * 128 + n]); }
    if (tid < 128) { be2s[tid] = be2[tid]; bn2s[tid] = bn2[tid]; }
    __syncthreads();

    const int lane = tid & 31, wid = tid >> 5;
    const int g = lane >> 2, q = lane & 3;
    const unsigned F = 0xFFFFFFFFu;
    uint32_t* buf  = (uint32_t*)(sm + OFF_SCR + wid * WS_BYTES);  // [64][36]
    float*    buff = (float*)buf;

    for (int t = blockIdx.x; t < ntiles; t += gridDim.x) {
        const int eb = t * TILE_E + wid * 64;

        // rows m = 2*mt + h -> warp-local rows {16mt + 8h + g}, mt=0..3
        int sidx[8], didx[8];
        #pragma unroll
        for (int m = 0; m < 8; m++) {
            int r = eb + 16 * (m >> 1) + 8 * (m & 1) + g;
            r = (r < E) ? r : (E - 1);
            sidx[m] = eidx[r];
            didx[m] = eidx[E + r];
        }
        // per-lane scatter destinations for row groups [0,32) and [32,64)
        int r0c = eb + lane;        r0c = (r0c < E) ? r0c : (E - 1);
        int r1c = eb + 32 + lane;   r1c = (r1c < E) ? r1c : (E - 1);
        const int dl0 = eidx[E + r0c];
        const int dl1 = eidx[E + r1c];

        // ======== L1 init: c1 = pre1 (float4 loads from permuted P) =======
        float c1[4][4][4];
        #pragma unroll
        for (int m = 0; m < 8; m++) {
            const int mt = m >> 1, h = m & 1;
            float4 u0 = *(const float4*)&g_P[(size_t)sidx[m] * 128 + q * 8];
            float4 u1 = *(const float4*)&g_P[(size_t)sidx[m] * 128 + q * 8 + 4];
            float4 v0 = *(const float4*)&g_P[(size_t)didx[m] * 128 + 32 + q * 8];
            float4 v1 = *(const float4*)&g_P[(size_t)didx[m] * 128 + 32 + q * 8 + 4];
            c1[mt][0][2*h] = u0.x + v0.x;  c1[mt][0][2*h+1] = u0.y + v0.y;
            c1[mt][1][2*h] = u0.z + v0.z;  c1[mt][1][2*h+1] = u0.w + v0.w;
            c1[mt][2][2*h] = u1.x + v1.x;  c1[mt][2][2*h+1] = u1.y + v1.y;
            c1[mt][3][2*h] = u1.z + v1.z;  c1[mt][3][2*h+1] = u1.w + v1.w;
        }

        // ======== L1 mainloop: stage ef half (64 rows x 32 cols) -> mma ===
        #pragma unroll
        for (int hf = 0; hf < 2; hf++) {
            __syncwarp();
            #pragma unroll
            for (int i = 0; i < 16; i++) {
                int idx = i * 32 + lane;            // 0..511
                int row = idx >> 3, c8 = idx & 7;
                int r = eb + row; r = (r < E) ? r : (E - 1);
                float4 v = *(const float4*)&ef[(size_t)r * 64 + hf * 32 + 4 * c8];
                uint4 w = { f2tf(v.x), f2tf(v.y), f2tf(v.z), f2tf(v.w) };
                *(uint4*)&buf[row * 36 + 4 * c8] = w;
            }
            __syncwarp();
            #pragma unroll
            for (int kt = 0; kt < 4; kt++) {
                uint32_t a[4][4];
                #pragma unroll
                for (int mt = 0; mt < 4; mt++) {
                    int r0 = (16*mt + g) * 36, r1 = (16*mt + 8 + g) * 36;
                    a[mt][0] = buf[r0 + 8*kt + q];
                    a[mt][1] = buf[r1 + 8*kt + q];
                    a[mt][2] = buf[r0 + 8*kt + q + 4];
                    a[mt][3] = buf[r1 + 8*kt + q + 4];
                }
                const int ktg = 4 * hf + kt;
                #pragma unroll
                for (int nt = 0; nt < 4; nt++) {
                    uint32_t b0 = W1s[(8*nt+g)*68 + 8*ktg + q];
                    uint32_t b1 = W1s[(8*nt+g)*68 + 8*ktg + q + 4];
                    #pragma unroll
                    for (int mt = 0; mt < 4; mt++)
                        mma8(c1[mt][nt], a[mt][0],a[mt][1],a[mt][2],a[mt][3], b0, b1);
                }
            }
        }
        // h1 -> buf (relu + tf32), reused across L2 K-chunks
        __syncwarp();
        #pragma unroll
        for (int mt = 0; mt < 4; mt++)
            #pragma unroll
            for (int nt = 0; nt < 4; nt++) {
                const int col = 8 * nt + 2 * q;
                uint2 v0 = { f2tf(fmaxf(c1[mt][nt][0], 0.f)), f2tf(fmaxf(c1[mt][nt][1], 0.f)) };
                uint2 v1 = { f2tf(fmaxf(c1[mt][nt][2], 0.f)), f2tf(fmaxf(c1[mt][nt][3], 0.f)) };
                *(uint2*)&buf[(16*mt + g) * 36 + col]     = v0;
                *(uint2*)&buf[(16*mt + 8 + g) * 36 + col] = v1;
            }
        __syncwarp();

        // ========== L2+L3 fused: h2(64x64) = relu(pre2 + em @ Wn1m) =======
        float c3[4][8][4];
        #pragma unroll
        for (int m = 0; m < 8; m++) {
            const int mt = m >> 1, h = m & 1;
            const float* Pp = &g_P[(size_t)didx[m] * 128 + 64 + q * 16];
            #pragma unroll
            for (int w = 0; w < 4; w++) {
                float4 v = *(const float4*)(Pp + 4 * w);
                c3[mt][2*w][2*h]     = v.x;  c3[mt][2*w][2*h+1]   = v.y;
                c3[mt][2*w+1][2*h]   = v.z;  c3[mt][2*w+1][2*h+1] = v.w;
            }
        }
        #pragma unroll 1
        for (int ch = 0; ch < 4; ch++) {
            // --- L2 chunk: em_c(64x32) = relu(be2_c + h1 @ We2_c) ---
            float c2[4][4][4];
            #pragma unroll
            for (int nt = 0; nt < 4; nt++) {
                float2 b = *(const float2*)&be2s[32*ch + 8*nt + 2*q];
                #pragma unroll
                for (int mt = 0; mt < 4; mt++) {
                    c2[mt][nt][0] = b.x; c2[mt][nt][1] = b.y;
                    c2[mt][nt][2] = b.x; c2[mt][nt][3] = b.y;
                }
            }
            #pragma unroll
            for (int kt = 0; kt < 4; kt++) {
                uint32_t a[4][4];
                #pragma unroll
                for (int mt = 0; mt < 4; mt++) {
                    int r0 = (16*mt + g) * 36, r1 = (16*mt + 8 + g) * 36;
                    a[mt][0] = buf[r0 + 8*kt + q];
                    a[mt][1] = buf[r1 + 8*kt + q];
                    a[mt][2] = buf[r0 + 8*kt + q + 4];
                    a[mt][3] = buf[r1 + 8*kt + q + 4];
                }
                #pragma unroll
                for (int nt = 0; nt < 4; nt++) {
                    uint32_t b0 = W2s[(32*ch + 8*nt + g)*36 + 8*kt + q];
                    uint32_t b1 = W2s[(32*ch + 8*nt + g)*36 + 8*kt + q + 4];
                    #pragma unroll
                    for (int mt = 0; mt < 4; mt++)
                        mma8(c2[mt][nt], a[mt][0],a[mt][1],a[mt][2],a[mt][3], b0, b1);
                }
            }
            // --- convert em C-frags to A-frags, accumulate L3 ---
            #pragma unroll
            for (int kt = 0; kt < 4; kt++) {
                uint32_t a[4][4];
                #pragma unroll
                for (int mt = 0; mt < 4; mt++)
                    frag_c2a(c2[mt][kt][0], c2[mt][kt][1], c2[mt][kt][2], c2[mt][kt][3],
                             lane, a[mt]);
                #pragma unroll
                for (int nt = 0; nt < 8; nt++) {
                    uint32_t b0 = W3s[(8*nt+g)*132 + 32*ch + 8*kt + q];
                    uint32_t b1 = W3s[(8*nt+g)*132 + 32*ch + 8*kt + q + 4];
                    #pragma unroll
                    for (int mt = 0; mt < 4; mt++)
                        mma8(c3[mt][nt], a[mt][0],a[mt][1],a[mt][2],a[mt][3], b0, b1);
                }
            }
        }

        // ---- h2 C-frags -> A-frags once (128 regs), reused by all n4 -----
        uint32_t h2a[8][4][4];
        #pragma unroll
        for (int kt = 0; kt < 8; kt++)
            #pragma unroll
            for (int mt = 0; mt < 4; mt++)
                frag_c2a(c3[mt][kt][0], c3[mt][kt][1], c3[mt][kt][2], c3[mt][kt][3],
                         lane, h2a[kt][mt]);

        // ============ L4: nm(64x128) = relu(bn2 + h2 @ Wn2), scatter ======
        #pragma unroll 1
        for (int n4 = 0; n4 < 4; n4++) {
            float c4[4][4][4];
            #pragma unroll
            for (int nt = 0; nt < 4; nt++) {
                float2 b = *(const float2*)&bn2s[32*n4 + 8*nt + 2*q];
                #pragma unroll
                for (int mt = 0; mt < 4; mt++) {
                    c4[mt][nt][0] = b.x; c4[mt][nt][1] = b.y;
                    c4[mt][nt][2] = b.x; c4[mt][nt][3] = b.y;
                }
            }
            #pragma unroll
            for (int kt = 0; kt < 8; kt++) {
                #pragma unroll
                for (int nt = 0; nt < 4; nt++) {
                    uint32_t b0 = W4s[(32*n4 + 8*nt + g)*68 + 8*kt + q];
                    uint32_t b1 = W4s[(32*n4 + 8*nt + g)*68 + 8*kt + q + 4];
                    #pragma unroll
                    for (int mt = 0; mt < 4; mt++)
                        mma8(c4[mt][nt], h2a[kt][mt][0],h2a[kt][mt][1],
                                         h2a[kt][mt][2],h2a[kt][mt][3], b0, b1);
                }
            }
            // transpose through smem -> row-coalesced red4
            __syncwarp();
            #pragma unroll
            for (int mt = 0; mt < 4; mt++)
                #pragma unroll
                for (int nt = 0; nt < 4; nt++) {
                    const int col = 8 * nt + 2 * q;
                    float2 v0 = { fmaxf(c4[mt][nt][0], 0.f), fmaxf(c4[mt][nt][1], 0.f) };
                    float2 v1 = { fmaxf(c4[mt][nt][2], 0.f), fmaxf(c4[mt][nt][3], 0.f) };
                    *(float2*)&buff[(16*mt + g) * 36 + col]     = v0;
                    *(float2*)&buff[(16*mt + 8 + g) * 36 + col] = v1;
                }
            __syncwarp();
            #pragma unroll
            for (int i = 0; i < 16; i++) {
                int row = 4 * i + (lane >> 3);           // 0..63
                float4 v = *(const float4*)&buff[row * 36 + 4 * (lane & 7)];
                int dr = __shfl_sync(F, (i < 8) ? dl0 : dl1, row & 31);
                if (eb + row < E)
                    red4(out + (size_t)dr * 128 + 32 * n4 + 4 * (lane & 7),
                         v.x, v.y, v.z, v.w);
            }
        }
    }
}

// ---------------------------------------------------------------------------
extern "C" void kernel_launch(void* const* d_in, const int* in_sizes, int n_in,
                              void* d_out, int out_size) {
    const float* nf  = (const float*)d_in[0];
    const float* ef  = (const float*)d_in[1];
    const int*   ei  = (const int*)  d_in[2];
    const float* We1 = (const float*)d_in[3];
    const float* be1 = (const float*)d_in[4];
    const float* We2 = (const float*)d_in[5];
    const float* be2 = (const float*)d_in[6];
    const float* Wn1 = (const float*)d_in[7];
    const float* bn1 = (const float*)d_in[8];
    const float* Wn2 = (const float*)d_in[9];
    const float* bn2 = (const float*)d_in[10];
    float* out = (float*)d_out;

    const int Nn = in_sizes[0] / 128;
    const int E  = in_sizes[2] / 2;
    const int ntiles = (E + TILE_E - 1) / TILE_E;

    precompute_kernel<<<(Nn + 15) / 16, 128>>>(nf, We1, be1, Wn1, bn1, out, Nn);

    cudaFuncSetAttribute(edge_mma_kernel,
                         cudaFuncAttributeMaxDynamicSharedMemorySize, SM_TOTAL);
    edge_mma_kernel<<<152, TPB, SM_TOTAL>>>(ef, ei, We1, We2, be2,
                                            Wn1, Wn2, bn2, out, E, ntiles);
}

// round 8
// speedup vs baseline: 1.5877x; 1.5877x over previous
#include <cuda_runtime.h>
#include <cuda_fp16.h>
#include <cstdint>

#define TPB 384
#define NWARP 12
#define TILE_E (NWARP * 32)
#define MAXN 50000

typedef unsigned long long u64;

// Per-node precomputed projections in FP16, COLUMN-PERMUTED:
// slice0 [0:32)  = nf@We1[0:128]+be1 (src),  pos = q*8  + nt*2 + b
// slice1 [32:64) = nf@We1[128:256]   (dst),  same perm within slice
// slice2 [64:128)= nf@Wn1[0:128]+bn1 (pre2), pos = q*16 + nt*2 + b
__device__ __align__(16) __half g_P[MAXN * 128];

// ------------------------------- helpers ----------------------------------
__device__ __forceinline__ uint32_t h2pack(float lo, float hi) {
    uint32_t r;  // cvt.rn.f16x2.f32 d, a, b  ->  d.hi = a, d.lo = b
    asm("cvt.rn.f16x2.f32 %0, %1, %2;" : "=r"(r) : "f"(hi), "f"(lo));
    return r;
}
__device__ __forceinline__ uint32_t h2relu(float c0, float c1) {
    return h2pack(fmaxf(c0, 0.f), fmaxf(c1, 0.f));
}
__device__ __forceinline__ void red4(float* p, float a, float b, float c, float d) {
    asm volatile("red.global.add.v4.f32 [%0], {%1,%2,%3,%4};"
                 :: "l"(p), "f"(a), "f"(b), "f"(c), "f"(d) : "memory");
}
__device__ __forceinline__ u64 pk2(float lo, float hi) {
    u64 r;
    asm("mov.b64 %0, {%1, %2};" : "=l"(r)
        : "r"(__float_as_uint(lo)), "r"(__float_as_uint(hi)));
    return r;
}
__device__ __forceinline__ float2 up2(u64 v) {
    unsigned lo, hi;
    asm("mov.b64 {%0, %1}, %2;" : "=r"(lo), "=r"(hi) : "l"(v));
    return make_float2(__uint_as_float(lo), __uint_as_float(hi));
}
__device__ __forceinline__ u64 fma2(u64 a, u64 b, u64 c) {
    u64 d;
    asm("fma.rn.f32x2 %0, %1, %2, %3;" : "=l"(d) : "l"(a), "l"(b), "l"(c));
    return d;
}
// D(16x8,f32) += A(16x16,f16) @ B(16x8,f16)
__device__ __forceinline__ void mma16(float* c, uint32_t a0, uint32_t a1,
                                      uint32_t a2, uint32_t a3,
                                      uint32_t b0, uint32_t b1) {
    asm volatile("mma.sync.aligned.m16n8k16.row.col.f32.f16.f16.f32 "
                 "{%0,%1,%2,%3}, {%4,%5,%6,%7}, {%8,%9}, {%0,%1,%2,%3};"
                 : "+f"(c[0]), "+f"(c[1]), "+f"(c[2]), "+f"(c[3])
                 : "r"(a0), "r"(a1), "r"(a2), "r"(a3), "r"(b0), "r"(b1));
}
// column permutation for g_P storage
__device__ __forceinline__ int permP(int j) {
    if (j < 64) {
        int s = j & 32, c = j & 31;
        return s + ((c >> 1) & 3) * 8 + (c >> 3) * 2 + (c & 1);
    }
    int c = j - 64;
    return 64 + ((c >> 1) & 3) * 16 + (c >> 3) * 2 + (c & 1);
}

// ---------------------------------------------------------------------------
// Precompute: 16 nodes/block, packed f32x2; stores f16 permuted columns;
// also initializes out = node_features.
// ---------------------------------------------------------------------------
__global__ void __launch_bounds__(128) precompute_kernel(
    const float* __restrict__ nf,
    const float* __restrict__ We1,
    const float* __restrict__ be1,
    const float* __restrict__ Wn1,
    const float* __restrict__ bn1,
    float* __restrict__ out, int Nn)
{
    __shared__ float nfs[16][128];
    const int nb  = blockIdx.x * 16;
    const int tid = threadIdx.x;

    #pragma unroll
    for (int i = 0; i < 16; i++) {
        int n = nb + i;
        if (n < Nn) {
            float v = nf[n * 128 + tid];
            nfs[i][tid] = v;
            out[n * 128 + tid] = v;
        } else nfs[i][tid] = 0.f;
    }
    __syncthreads();

    const int j = tid;
    const float* wcol; int stride; float bias;
    if (j < 32)      { wcol = We1 + j;                 stride = 32; bias = be1[j]; }
    else if (j < 64) { wcol = We1 + 128 * 32 + (j-32); stride = 32; bias = 0.f; }
    else             { wcol = Wn1 + (j - 64);          stride = 64; bias = bn1[j-64]; }

    u64 acc2[16];
    #pragma unroll
    for (int i = 0; i < 16; i++) acc2[i] = pk2(bias, 0.f);

    #pragma unroll 2
    for (int k = 0; k < 128; k += 2) {
        u64 w2 = pk2(wcol[k * stride], wcol[(k + 1) * stride]);
        #pragma unroll
        for (int i = 0; i < 16; i++) {
            float2 v = *(const float2*)&nfs[i][k];
            acc2[i] = fma2(pk2(v.x, v.y), w2, acc2[i]);
        }
    }
    const int pj = permP(j);
    #pragma unroll
    for (int i = 0; i < 16; i++) {
        int n = nb + i;
        if (n < Nn) {
            float2 f = up2(acc2[i]);
            g_P[n * 128 + pj] = __float2half(f.x + f.y);
        }
    }
}

// ---------------------------------------------------------------------------
// Edge kernel: persistent, 12 independent warps x 32 edges, mma.sync FP16
// (f32 accumulate). Weights f16x2 in smem; activations pass layer-to-layer
// via in-register C->A packing (no shuffles, no smem except h1/ef staging).
// ---------------------------------------------------------------------------
#define OFF_W1  0            // [32 n][36 w]  f16x2 words -> 4608 B
#define OFF_W2  4608         // [128][20]     -> 10240 B
#define OFF_W3  14848        // [64][68]      -> 17408 B
#define OFF_W4  32256        // [128][36]     -> 18432 B
#define OFF_BE2 50688
#define OFF_BN2 51200
#define OFF_SCR 51712
#define WS_BYTES 4608        // per-warp buffer (ef f16 / h1 f16 / nm f32)
#define SM_TOTAL (OFF_SCR + NWARP * WS_BYTES)   // 107008

__global__ void __launch_bounds__(TPB, 1) edge_mma_kernel(
    const float* __restrict__ ef,
    const int*   __restrict__ eidx,
    const float* __restrict__ We1,
    const float* __restrict__ We2,
    const float* __restrict__ be2,
    const float* __restrict__ Wn1,
    const float* __restrict__ Wn2,
    const float* __restrict__ bn2,
    float* __restrict__ out, int E, int ntiles)
{
    extern __shared__ char sm[];
    uint32_t* W1s = (uint32_t*)(sm + OFF_W1);
    uint32_t* W2s = (uint32_t*)(sm + OFF_W2);
    uint32_t* W3s = (uint32_t*)(sm + OFF_W3);
    uint32_t* W4s = (uint32_t*)(sm + OFF_W4);
    float* be2s = (float*)(sm + OFF_BE2);
    float* bn2s = (float*)(sm + OFF_BN2);

    const int tid = threadIdx.x;
    // stage weights transposed [n][k-pair] as f16x2 words
    {
        const float* W = We1 + 256 * 32;             // edge rows of We1 [64k][32n]
        for (int i = tid; i < 32 * 32; i += TPB) {
            int n = i >> 5, w = i & 31;
            W1s[n*36 + w] = h2pack(W[(2*w)*32 + n], W[(2*w+1)*32 + n]);
        }
        for (int i = tid; i < 128 * 16; i += TPB) {  // We2 [32k][128n]
            int n = i >> 4, w = i & 15;
            W2s[n*20 + w] = h2pack(We2[(2*w)*128 + n], We2[(2*w+1)*128 + n]);
        }
        const float* W3 = Wn1 + 128 * 64;            // msg rows of Wn1 [128k][64n]
        for (int i = tid; i < 64 * 64; i += TPB) {
            int n = i >> 6, w = i & 63;
            W3s[n*68 + w] = h2pack(W3[(2*w)*64 + n], W3[(2*w+1)*64 + n]);
        }
        for (int i = tid; i < 128 * 32; i += TPB) {  // Wn2 [64k][128n]
            int n = i >> 5, w = i & 31;
            W4s[n*36 + w] = h2pack(Wn2[(2*w)*128 + n], Wn2[(2*w+1)*128 + n]);
        }
    }
    if (tid < 128) { be2s[tid] = be2[tid]; bn2s[tid] = bn2[tid]; }
    __syncthreads();

    const int lane = tid & 31, wid = tid >> 5;
    const int g = lane >> 2, q = lane & 3;
    const unsigned F = 0xFFFFFFFFu;
    uint32_t* buf  = (uint32_t*)(sm + OFF_SCR + wid * WS_BYTES);
    float*    buff = (float*)buf;

    for (int t = blockIdx.x; t < ntiles; t += gridDim.x) {
        const int eb = t * TILE_E + wid * 32;

        // rows m = 2*mt + h -> warp-local rows {16mt + 8h + g}
        int sidx[4], didx[4];
        #pragma unroll
        for (int m = 0; m < 4; m++) {
            int r = eb + 16 * (m >> 1) + 8 * (m & 1) + g;
            r = (r < E) ? r : (E - 1);
            sidx[m] = eidx[r];
            didx[m] = eidx[E + r];
        }
        int rl = eb + lane; rl = (rl < E) ? rl : (E - 1);
        const int dl = eidx[E + rl];

        // ======== L1 init: c1 = pre1 (f16 uint4 loads, permuted P) ========
        float c1[2][4][4];
        #pragma unroll
        for (int m = 0; m < 4; m++) {
            const int mt = m >> 1, h = m & 1;
            uint4 us = *(const uint4*)&g_P[(size_t)sidx[m] * 128 + q * 8];
            uint4 ud = *(const uint4*)&g_P[(size_t)didx[m] * 128 + 32 + q * 8];
            const uint32_t* sw = (const uint32_t*)&us;
            const uint32_t* dw = (const uint32_t*)&ud;
            #pragma unroll
            for (int nt = 0; nt < 4; nt++) {
                float2 a = __half22float2(*(const __half2*)&sw[nt]);
                float2 b = __half22float2(*(const __half2*)&dw[nt]);
                c1[mt][nt][2*h]   = a.x + b.x;
                c1[mt][nt][2*h+1] = a.y + b.y;
            }
        }

        // ======== stage ef (32 rows x 64 cols f32 -> f16x2 words) =========
        __syncwarp();
        #pragma unroll
        for (int i = 0; i < 16; i++) {
            int idx = i * 32 + lane;                // 0..511
            int row = idx >> 4, c16 = idx & 15;
            int r = eb + row; r = (r < E) ? r : (E - 1);
            float4 v = *(const float4*)&ef[(size_t)r * 64 + 4 * c16];
            uint2 w = { h2pack(v.x, v.y), h2pack(v.z, v.w) };
            *(uint2*)&buf[row * 36 + 2 * c16] = w;
        }
        __syncwarp();

        // ======== L1 mainloop: K=64 -> 4 k16 chunks ========================
        #pragma unroll
        for (int kt = 0; kt < 4; kt++) {
            uint32_t a[2][4];
            #pragma unroll
            for (int mt = 0; mt < 2; mt++) {
                int r0 = (16*mt + g) * 36, r1 = (16*mt + 8 + g) * 36;
                a[mt][0] = buf[r0 + 8*kt + q];
                a[mt][1] = buf[r1 + 8*kt + q];
                a[mt][2] = buf[r0 + 8*kt + q + 4];
                a[mt][3] = buf[r1 + 8*kt + q + 4];
            }
            #pragma unroll
            for (int nt = 0; nt < 4; nt++) {
                uint32_t b0 = W1s[(8*nt+g)*36 + 8*kt + q];
                uint32_t b1 = W1s[(8*nt+g)*36 + 8*kt + q + 4];
                mma16(c1[0][nt], a[0][0],a[0][1],a[0][2],a[0][3], b0, b1);
                mma16(c1[1][nt], a[1][0],a[1][1],a[1][2],a[1][3], b0, b1);
            }
        }
        // h1 -> buf as f16x2 (pitch 20 words), reused by 4 L2 K-passes
        __syncwarp();
        #pragma unroll
        for (int mt = 0; mt < 2; mt++)
            #pragma unroll
            for (int nt = 0; nt < 4; nt++) {
                buf[(16*mt + g) * 20 + 4*nt + q]     = h2relu(c1[mt][nt][0], c1[mt][nt][1]);
                buf[(16*mt + 8 + g) * 20 + 4*nt + q] = h2relu(c1[mt][nt][2], c1[mt][nt][3]);
            }
        __syncwarp();

        // ========== L2+L3 fused: h2(32x64) = relu(pre2 + em @ Wn1m) =======
        float c3[2][8][4];
        #pragma unroll
        for (int m = 0; m < 4; m++) {
            const int mt = m >> 1, h = m & 1;
            const __half* Pp = &g_P[(size_t)didx[m] * 128 + 64 + q * 16];
            uint4 p0 = *(const uint4*)Pp;
            uint4 p1 = *(const uint4*)(Pp + 8);
            const uint32_t* w0 = (const uint32_t*)&p0;
            const uint32_t* w1 = (const uint32_t*)&p1;
            #pragma unroll
            for (int nt = 0; nt < 4; nt++) {
                float2 a = __half22float2(*(const __half2*)&w0[nt]);
                float2 b = __half22float2(*(const __half2*)&w1[nt]);
                c3[mt][nt][2*h]     = a.x;  c3[mt][nt][2*h+1]     = a.y;
                c3[mt][nt+4][2*h]   = b.x;  c3[mt][nt+4][2*h+1]   = b.y;
            }
        }
        #pragma unroll
        for (int ch = 0; ch < 4; ch++) {
            // --- L2 chunk: em_c(32x32) = relu(be2_c + h1 @ We2_c) ---
            float c2[2][4][4];
            #pragma unroll
            for (int nt = 0; nt < 4; nt++) {
                float2 b = *(const float2*)&be2s[32*ch + 8*nt + 2*q];
                #pragma unroll
                for (int mt = 0; mt < 2; mt++) {
                    c2[mt][nt][0] = b.x; c2[mt][nt][1] = b.y;
                    c2[mt][nt][2] = b.x; c2[mt][nt][3] = b.y;
                }
            }
            #pragma unroll
            for (int kt = 0; kt < 2; kt++) {
                uint32_t a[2][4];
                #pragma unroll
                for (int mt = 0; mt < 2; mt++) {
                    int r0 = (16*mt + g) * 20, r1 = (16*mt + 8 + g) * 20;
                    a[mt][0] = buf[r0 + 8*kt + q];
                    a[mt][1] = buf[r1 + 8*kt + q];
                    a[mt][2] = buf[r0 + 8*kt + q + 4];
                    a[mt][3] = buf[r1 + 8*kt + q + 4];
                }
                #pragma unroll
                for (int nt = 0; nt < 4; nt++) {
                    uint32_t b0 = W2s[(32*ch + 8*nt + g)*20 + 8*kt + q];
                    uint32_t b1 = W2s[(32*ch + 8*nt + g)*20 + 8*kt + q + 4];
                    mma16(c2[0][nt], a[0][0],a[0][1],a[0][2],a[0][3], b0, b1);
                    mma16(c2[1][nt], a[1][0],a[1][1],a[1][2],a[1][3], b0, b1);
                }
            }
            // --- em C-frags -> A-frags by LOCAL packing (no shuffles) ---
            #pragma unroll
            for (int kc = 0; kc < 2; kc++) {
                uint32_t a[2][4];
                #pragma unroll
                for (int mt = 0; mt < 2; mt++) {
                    a[mt][0] = h2relu(c2[mt][2*kc][0],   c2[mt][2*kc][1]);
                    a[mt][1] = h2relu(c2[mt][2*kc][2],   c2[mt][2*kc][3]);
                    a[mt][2] = h2relu(c2[mt][2*kc+1][0], c2[mt][2*kc+1][1]);
                    a[mt][3] = h2relu(c2[mt][2*kc+1][2], c2[mt][2*kc+1][3]);
                }
                const int ktg = 2 * ch + kc;
                #pragma unroll
                for (int nt = 0; nt < 8; nt++) {
                    uint32_t b0 = W3s[(8*nt+g)*68 + 8*ktg + q];
                    uint32_t b1 = W3s[(8*nt+g)*68 + 8*ktg + q + 4];
                    mma16(c3[0][nt], a[0][0],a[0][1],a[0][2],a[0][3], b0, b1);
                    mma16(c3[1][nt], a[1][0],a[1][1],a[1][2],a[1][3], b0, b1);
                }
            }
        }

        // ---- h2 C-frags -> A-frags once (32 regs), local packing ---------
        uint32_t h2a[4][2][4];
        #pragma unroll
        for (int kc = 0; kc < 4; kc++)
            #pragma unroll
            for (int mt = 0; mt < 2; mt++) {
                h2a[kc][mt][0] = h2relu(c3[mt][2*kc][0],   c3[mt][2*kc][1]);
                h2a[kc][mt][1] = h2relu(c3[mt][2*kc][2],   c3[mt][2*kc][3]);
                h2a[kc][mt][2] = h2relu(c3[mt][2*kc+1][0], c3[mt][2*kc+1][1]);
                h2a[kc][mt][3] = h2relu(c3[mt][2*kc+1][2], c3[mt][2*kc+1][3]);
            }

        // ============ L4: nm(32x128) = relu(bn2 + h2 @ Wn2), scatter ======
        #pragma unroll
        for (int n4 = 0; n4 < 4; n4++) {
            float c4[2][4][4];
            #pragma unroll
            for (int nt = 0; nt < 4; nt++) {
                float2 b = *(const float2*)&bn2s[32*n4 + 8*nt + 2*q];
                #pragma unroll
                for (int mt = 0; mt < 2; mt++) {
                    c4[mt][nt][0] = b.x; c4[mt][nt][1] = b.y;
                    c4[mt][nt][2] = b.x; c4[mt][nt][3] = b.y;
                }
            }
            #pragma unroll
            for (int kt = 0; kt < 4; kt++) {
                #pragma unroll
                for (int nt = 0; nt < 4; nt++) {
                    uint32_t b0 = W4s[(32*n4 + 8*nt + g)*36 + 8*kt + q];
                    uint32_t b1 = W4s[(32*n4 + 8*nt + g)*36 + 8*kt + q + 4];
                    mma16(c4[0][nt], h2a[kt][0][0],h2a[kt][0][1],h2a[kt][0][2],h2a[kt][0][3], b0, b1);
                    mma16(c4[1][nt], h2a[kt][1][0],h2a[kt][1][1],h2a[kt][1][2],h2a[kt][1][3], b0, b1);
                }
            }
            // transpose through smem -> row-coalesced red4
            __syncwarp();
            #pragma unroll
            for (int mt = 0; mt < 2; mt++)
                #pragma unroll
                for (int nt = 0; nt < 4; nt++) {
                    const int col = 8 * nt + 2 * q;
                    float2 v0 = { fmaxf(c4[mt][nt][0], 0.f), fmaxf(c4[mt][nt][1], 0.f) };
                    float2 v1 = { fmaxf(c4[mt][nt][2], 0.f), fmaxf(c4[mt][nt][3], 0.f) };
                    *(float2*)&buff[(16*mt + g) * 36 + col]     = v0;
                    *(float2*)&buff[(16*mt + 8 + g) * 36 + col] = v1;
                }
            __syncwarp();
            #pragma unroll
            for (int i = 0; i < 8; i++) {
                int row = 4 * i + (lane >> 3);
                float4 v = *(const float4*)&buff[row * 36 + 4 * (lane & 7)];
                int dr = __shfl_sync(F, dl, row);
                if (eb + row < E)
                    red4(out + (size_t)dr * 128 + 32 * n4 + 4 * (lane & 7),
                         v.x, v.y, v.z, v.w);
            }
        }
    }
}

// ---------------------------------------------------------------------------
extern "C" void kernel_launch(void* const* d_in, const int* in_sizes, int n_in,
                              void* d_out, int out_size) {
    const float* nf  = (const float*)d_in[0];
    const float* ef  = (const float*)d_in[1];
    const int*   ei  = (const int*)  d_in[2];
    const float* We1 = (const float*)d_in[3];
    const float* be1 = (const float*)d_in[4];
    const float* We2 = (const float*)d_in[5];
    const float* be2 = (const float*)d_in[6];
    const float* Wn1 = (const float*)d_in[7];
    const float* bn1 = (const float*)d_in[8];
    const float* Wn2 = (const float*)d_in[9];
    const float* bn2 = (const float*)d_in[10];
    float* out = (float*)d_out;

    const int Nn = in_sizes[0] / 128;
    const int E  = in_sizes[2] / 2;
    const int ntiles = (E + TILE_E - 1) / TILE_E;

    precompute_kernel<<<(Nn + 15) / 16, 128>>>(nf, We1, be1, Wn1, bn1, out, Nn);

    cudaFuncSetAttribute(edge_mma_kernel,
                         cudaFuncAttributeMaxDynamicSharedMemorySize, SM_TOTAL);
    edge_mma_kernel<<<152, TPB, SM_TOTAL>>>(ef, ei, We1, We2, be2,
                                            Wn1, Wn2, bn2, out, E, ntiles);
}